// round 2
// baseline (speedup 1.0000x reference)
#include <cuda_runtime.h>
#include <math.h>

#define BDIM 16
#define TDIM 2048
#define CDIM 1024
#define HDIM 64
#define MROWS (BDIM * TDIM)   // 32768 total rows

// Scratch for projected Q, K, V  (each [B*T, 64] f32) — device globals, no allocs.
__device__ float g_Q[MROWS * HDIM];
__device__ float g_K[MROWS * HDIM];
__device__ float g_V[MROWS * HDIM];

// ---------------------------------------------------------------------------
// Kernel 1: fused QKV projection.  C = x[32768,1024] @ [wq|wk|wv][1024,192]
// Block tile 64x192, K-tile 32, 256 threads, 4x12 per-thread micro-tile.
// ---------------------------------------------------------------------------
#define PBM 64
#define PBN 192
#define PBK 32

__global__ __launch_bounds__(256) void qkv_proj_kernel(
    const float* __restrict__ x,
    const float* __restrict__ wq,
    const float* __restrict__ wk,
    const float* __restrict__ wv)
{
    __shared__ float As[PBM][PBK + 1];   // +1 pad: conflict-free row reads
    __shared__ float Ws[PBK][PBN];

    const int tid = threadIdx.x;
    const int tx  = tid & 15;            // 0..15 -> 12-col strip
    const int ty  = tid >> 4;            // 0..15 -> 4-row strip
    const int m0  = blockIdx.x * PBM;

    float acc[4][12];
    #pragma unroll
    for (int i = 0; i < 4; i++)
        #pragma unroll
        for (int j = 0; j < 12; j++) acc[i][j] = 0.f;

    for (int k0 = 0; k0 < CDIM; k0 += PBK) {
        // --- load x tile: 64x32 floats = 512 float4, 2 per thread, coalesced
        #pragma unroll
        for (int i = 0; i < 2; i++) {
            int idx = tid + i * 256;     // float4 index
            int r   = idx >> 3;          // 8 float4 per row
            int c4  = idx & 7;
            float4 v = *(const float4*)&x[(size_t)(m0 + r) * CDIM + k0 + c4 * 4];
            As[r][c4 * 4 + 0] = v.x;
            As[r][c4 * 4 + 1] = v.y;
            As[r][c4 * 4 + 2] = v.z;
            As[r][c4 * 4 + 3] = v.w;
        }
        // --- load w tile: 32x192 floats = 1536 float4, 6 per thread
        #pragma unroll
        for (int i = 0; i < 6; i++) {
            int idx = tid + i * 256;     // float4 index
            int kk  = idx / 48;          // 48 float4 per k-row (192 cols)
            int n4  = idx % 48;
            const float* wp = (n4 < 16) ? wq : ((n4 < 32) ? wk : wv);
            int nc = (n4 & 15) * 4;
            float4 v = *(const float4*)&wp[(size_t)(k0 + kk) * HDIM + nc];
            *(float4*)&Ws[kk][n4 * 4] = v;
        }
        __syncthreads();

        #pragma unroll
        for (int kk = 0; kk < PBK; kk++) {
            float a[4];
            #pragma unroll
            for (int i = 0; i < 4; i++) a[i] = As[ty * 4 + i][kk];
            float4 b0 = *(const float4*)&Ws[kk][tx * 12 + 0];
            float4 b1 = *(const float4*)&Ws[kk][tx * 12 + 4];
            float4 b2 = *(const float4*)&Ws[kk][tx * 12 + 8];
            float b[12] = {b0.x,b0.y,b0.z,b0.w, b1.x,b1.y,b1.z,b1.w, b2.x,b2.y,b2.z,b2.w};
            #pragma unroll
            for (int i = 0; i < 4; i++)
                #pragma unroll
                for (int j = 0; j < 12; j++)
                    acc[i][j] = fmaf(a[i], b[j], acc[i][j]);
        }
        __syncthreads();
    }

    // --- write out into Q/K/V scratch
    #pragma unroll
    for (int i = 0; i < 4; i++) {
        int r = m0 + ty * 4 + i;
        #pragma unroll
        for (int j = 0; j < 12; j++) {
            int n   = tx * 12 + j;
            int mtx = n >> 6;        // 0=Q 1=K 2=V
            int h   = n & 63;
            float* dst = (mtx == 0) ? g_Q : ((mtx == 1) ? g_K : g_V);
            dst[(size_t)r * HDIM + h] = acc[i][j];
        }
    }
}

// ---------------------------------------------------------------------------
// Kernel 2: flash attention (causal).  128 threads = 128 query rows per CTA.
// KV tiles of 64 keys.  Scores staged in padded smem P tile (conflict-free).
// ---------------------------------------------------------------------------
#define QTILE 128
#define KTILE 64

__global__ __launch_bounds__(128) void attn_kernel(float* __restrict__ out)
{
    __shared__ float Ks[KTILE][HDIM];
    __shared__ float Vs[KTILE][HDIM];
    __shared__ float Ps[QTILE][KTILE + 1];   // +1 pad -> conflict-free per-row access

    const int b  = blockIdx.y;
    const int qt = gridDim.x - 1 - blockIdx.x;   // heavy tiles launch first
    const int r  = threadIdx.x;
    const int t  = qt * QTILE + r;               // global query position
    const size_t grow = (size_t)b * TDIM + t;

    // load my query row into registers
    float q[HDIM];
    {
        const float4* qsrc = (const float4*)&g_Q[grow * HDIM];
        #pragma unroll
        for (int i = 0; i < 16; i++) ((float4*)q)[i] = qsrc[i];
    }

    float acc[HDIM];
    #pragma unroll
    for (int h = 0; h < HDIM; h++) acc[h] = 0.f;
    float m = -INFINITY;
    float l = 0.f;

    const int ntiles = qt * 2 + 2;   // covers kv up to the causal diagonal

    for (int kt = 0; kt < ntiles; kt++) {
        const int kv0 = kt * KTILE;

        __syncthreads();   // previous tile fully consumed
        {
            const float4* ksrc = (const float4*)&g_K[((size_t)b * TDIM + kv0) * HDIM];
            const float4* vsrc = (const float4*)&g_V[((size_t)b * TDIM + kv0) * HDIM];
            float4* kd = (float4*)&Ks[0][0];
            float4* vd = (float4*)&Vs[0][0];
            #pragma unroll
            for (int i = 0; i < 8; i++) {   // 1024 float4 / 128 threads
                kd[r + i * 128] = ksrc[r + i * 128];
                vd[r + i * 128] = vsrc[r + i * 128];
            }
        }
        __syncthreads();

        const int jlim = min(KTILE, t - kv0 + 1);   // causal bound (<=0 -> skip)

        float tmax = -INFINITY;
        for (int j = 0; j < jlim; j++) {
            float s = 0.f;
            const float4* krow = (const float4*)&Ks[j][0];
            #pragma unroll
            for (int h4 = 0; h4 < 16; h4++) {
                float4 kv = krow[h4];                 // broadcast LDS.128
                s = fmaf(q[h4*4+0], kv.x, s);
                s = fmaf(q[h4*4+1], kv.y, s);
                s = fmaf(q[h4*4+2], kv.z, s);
                s = fmaf(q[h4*4+3], kv.w, s);
            }
            s *= 0.125f;                              // 1/sqrt(64)
            Ps[r][j] = s;
            tmax = fmaxf(tmax, s);
        }

        const float mnew = fmaxf(m, tmax);
        const float corr = __expf(m - mnew);          // 0 on first tile (m=-inf)
        l *= corr;
        #pragma unroll
        for (int h = 0; h < HDIM; h++) acc[h] *= corr;

        for (int j = 0; j < jlim; j++) {
            float p = __expf(Ps[r][j] - mnew);
            l += p;
            const float4* vrow = (const float4*)&Vs[j][0];
            #pragma unroll
            for (int h4 = 0; h4 < 16; h4++) {
                float4 vv = vrow[h4];                 // broadcast LDS.128
                acc[h4*4+0] = fmaf(p, vv.x, acc[h4*4+0]);
                acc[h4*4+1] = fmaf(p, vv.y, acc[h4*4+1]);
                acc[h4*4+2] = fmaf(p, vv.z, acc[h4*4+2]);
                acc[h4*4+3] = fmaf(p, vv.w, acc[h4*4+3]);
            }
        }
        m = mnew;
    }

    const float inv = 1.f / l;
    float4* od = (float4*)&out[grow * HDIM];
    #pragma unroll
    for (int i = 0; i < 16; i++) {
        float4 o;
        o.x = acc[i*4+0] * inv;
        o.y = acc[i*4+1] * inv;
        o.z = acc[i*4+2] * inv;
        o.w = acc[i*4+3] * inv;
        od[i] = o;
    }
}

// ---------------------------------------------------------------------------
extern "C" void kernel_launch(void* const* d_in, const int* in_sizes, int n_in,
                              void* d_out, int out_size)
{
    const float* x  = (const float*)d_in[0];
    const float* wq = (const float*)d_in[1];
    const float* wk = (const float*)d_in[2];
    const float* wv = (const float*)d_in[3];
    float* out = (float*)d_out;

    qkv_proj_kernel<<<MROWS / PBM, 256>>>(x, wq, wk, wv);
    attn_kernel<<<dim3(TDIM / QTILE, BDIM), 128>>>(out);
}

// round 4
// speedup vs baseline: 1.3908x; 1.3908x over previous
#include <cuda_runtime.h>
#include <math.h>
#include <cstdint>

#define BDIM 16
#define TDIM 2048
#define CDIM 1024
#define HDIM 64
#define MROWS (BDIM * TDIM)   // 32768

// Scratch for projected Q, K, V (device globals: no allocations).
__device__ __align__(16) float g_Q[MROWS * HDIM];
__device__ __align__(16) float g_K[MROWS * HDIM];
__device__ __align__(16) float g_V[MROWS * HDIM];

static __device__ __forceinline__ uint32_t f2tf32(float f) {
    uint32_t u;
    asm("cvt.rna.tf32.f32 %0, %1;" : "=r"(u) : "f"(f));
    return u;
}

// ---------------------------------------------------------------------------
// Kernel 1: QKV projection via mma.sync tf32 (arch-portable tensor path).
//   D[32768,192] = tf32(x)[32768,1024] @ tf32([wq|wk|wv])[1024,192]
// CTA tile 64x192, K-chunk 16, 128 threads (4 warps, 2m x 2n, warp 32x96).
// ---------------------------------------------------------------------------
#define BM 64
#define BN 192
#define BK 16
#define ASTR 20     // A row stride in words (conflict-free frag reads)
#define BSTR 200    // B k-row stride in words (conflict-free frag reads)
#define NCH (CDIM / BK)   // 64

__global__ __launch_bounds__(128) void qkv_proj_mma(
    const float* __restrict__ x,
    const float* __restrict__ wq,
    const float* __restrict__ wk,
    const float* __restrict__ wv)
{
    __shared__ uint32_t As[2][BM * ASTR];   // [m][k] tf32 bits
    __shared__ uint32_t Bs[2][BK * BSTR];   // [k][n] tf32 bits

    const int tid  = threadIdx.x;
    const int wid  = tid >> 5;
    const int lane = tid & 31;
    const int gid  = lane >> 2;    // 0..7
    const int tg   = lane & 3;     // 0..3
    const int wm   = (wid & 1) * 32;    // warp m offset
    const int wn   = (wid >> 1) * 96;   // warp n offset
    const int m0   = blockIdx.x * BM;

    float acc[2][12][4];
    #pragma unroll
    for (int mi = 0; mi < 2; mi++)
        #pragma unroll
        for (int ni = 0; ni < 12; ni++)
            #pragma unroll
            for (int k = 0; k < 4; k++) acc[mi][ni][k] = 0.f;

    float4 ra[2];
    float4 rb[6];

    auto gload = [&](int c) {
        #pragma unroll
        for (int i = 0; i < 2; i++) {
            int idx = tid + i * 128;            // 256 float4 slots (64x16)
            int row = idx >> 2, c4 = idx & 3;
            ra[i] = *(const float4*)&x[(size_t)(m0 + row) * CDIM + c * BK + c4 * 4];
        }
        #pragma unroll
        for (int i = 0; i < 6; i++) {
            int idx = tid + i * 128;            // 768 float4 slots (16x192)
            int k = idx / 48, n4 = idx % 48;
            const float* wp = (n4 < 16) ? wq : ((n4 < 32) ? wk : wv);
            rb[i] = *(const float4*)&wp[(size_t)(c * BK + k) * HDIM + (n4 & 15) * 4];
        }
    };
    auto sstore = [&](int s) {
        #pragma unroll
        for (int i = 0; i < 2; i++) {
            int idx = tid + i * 128;
            int row = idx >> 2, c4 = idx & 3;
            uint4 t = {f2tf32(ra[i].x), f2tf32(ra[i].y), f2tf32(ra[i].z), f2tf32(ra[i].w)};
            *(uint4*)&As[s][row * ASTR + c4 * 4] = t;
        }
        #pragma unroll
        for (int i = 0; i < 6; i++) {
            int idx = tid + i * 128;
            int k = idx / 48, n4 = idx % 48;
            uint4 t = {f2tf32(rb[i].x), f2tf32(rb[i].y), f2tf32(rb[i].z), f2tf32(rb[i].w)};
            *(uint4*)&Bs[s][k * BSTR + n4 * 4] = t;
        }
    };

    gload(0);
    sstore(0);
    __syncthreads();

    for (int c = 0; c < NCH; c++) {
        const int s = c & 1;
        if (c + 1 < NCH) gload(c + 1);

        #pragma unroll
        for (int ks = 0; ks < 2; ks++) {
            const int k0 = ks * 8;
            uint32_t a[2][4];
            #pragma unroll
            for (int mi = 0; mi < 2; mi++) {
                int r = wm + mi * 16 + gid;
                a[mi][0] = As[s][r * ASTR + k0 + tg];
                a[mi][1] = As[s][(r + 8) * ASTR + k0 + tg];
                a[mi][2] = As[s][r * ASTR + k0 + tg + 4];
                a[mi][3] = As[s][(r + 8) * ASTR + k0 + tg + 4];
            }
            #pragma unroll
            for (int ni = 0; ni < 12; ni++) {
                int n = wn + ni * 8 + gid;
                uint32_t b0 = Bs[s][(k0 + tg) * BSTR + n];
                uint32_t b1 = Bs[s][(k0 + tg + 4) * BSTR + n];
                #pragma unroll
                for (int mi = 0; mi < 2; mi++) {
                    asm volatile(
                        "mma.sync.aligned.m16n8k8.row.col.f32.tf32.tf32.f32 "
                        "{%0,%1,%2,%3}, {%4,%5,%6,%7}, {%8,%9}, {%0,%1,%2,%3};"
                        : "+f"(acc[mi][ni][0]), "+f"(acc[mi][ni][1]),
                          "+f"(acc[mi][ni][2]), "+f"(acc[mi][ni][3])
                        : "r"(a[mi][0]), "r"(a[mi][1]), "r"(a[mi][2]), "r"(a[mi][3]),
                          "r"(b0), "r"(b1));
                }
            }
        }

        if (c + 1 < NCH) sstore(s ^ 1);
        __syncthreads();
    }

    // Epilogue: c0/c1 at (row=gid, col=2tg,2tg+1); c2/c3 at row=gid+8.
    #pragma unroll
    for (int mi = 0; mi < 2; mi++) {
        #pragma unroll
        for (int ni = 0; ni < 12; ni++) {
            int n   = wn + ni * 8 + tg * 2;
            int sec = n >> 6;
            int h   = n & 63;
            float* dst = (sec == 0) ? g_Q : ((sec == 1) ? g_K : g_V);
            int r0 = m0 + wm + mi * 16 + gid;
            *(float2*)&dst[(size_t)r0 * HDIM + h] =
                make_float2(acc[mi][ni][0], acc[mi][ni][1]);
            *(float2*)&dst[(size_t)(r0 + 8) * HDIM + h] =
                make_float2(acc[mi][ni][2], acc[mi][ni][3]);
        }
    }
}

// ---------------------------------------------------------------------------
// Kernel 2: flash attention (causal), fp32 scalar, chain-broken dots.
// 128 threads = 128 query rows per CTA; KV tiles of 64.
// ---------------------------------------------------------------------------
#define QTILE 128
#define KTILE 64

__global__ __launch_bounds__(128) void attn_kernel(float* __restrict__ out)
{
    __shared__ float Ks[KTILE][HDIM];
    __shared__ float Vs[KTILE][HDIM];
    __shared__ float Ps[QTILE][KTILE + 1];

    const int b  = blockIdx.y;
    const int qt = gridDim.x - 1 - blockIdx.x;      // heavy tiles first
    const int r  = threadIdx.x;
    const int t  = qt * QTILE + r;
    const size_t grow = (size_t)b * TDIM + t;

    float q[HDIM];
    {
        const float4* qsrc = (const float4*)&g_Q[grow * HDIM];
        #pragma unroll
        for (int i = 0; i < 16; i++) ((float4*)q)[i] = qsrc[i];
        #pragma unroll
        for (int h = 0; h < HDIM; h++) q[h] *= 0.125f;   // fold in 1/sqrt(64)
    }

    float acc[HDIM];
    #pragma unroll
    for (int h = 0; h < HDIM; h++) acc[h] = 0.f;
    float m = -INFINITY;
    float l = 0.f;

    const int ntiles = qt * 2 + 2;

    for (int kt = 0; kt < ntiles; kt++) {
        const int kv0 = kt * KTILE;

        __syncthreads();
        {
            const float4* ksrc = (const float4*)&g_K[((size_t)b * TDIM + kv0) * HDIM];
            const float4* vsrc = (const float4*)&g_V[((size_t)b * TDIM + kv0) * HDIM];
            float4* kd = (float4*)&Ks[0][0];
            float4* vd = (float4*)&Vs[0][0];
            #pragma unroll
            for (int i = 0; i < 8; i++) {
                kd[r + i * 128] = ksrc[r + i * 128];
                vd[r + i * 128] = vsrc[r + i * 128];
            }
        }
        __syncthreads();

        const int jlim = min(KTILE, t - kv0 + 1);

        // pass 1: scores (j unrolled x2, 4 partial chains each)
        float tmax = -INFINITY;
        int j = 0;
        for (; j + 1 < jlim; j += 2) {
            const float4* k0r = (const float4*)&Ks[j][0];
            const float4* k1r = (const float4*)&Ks[j + 1][0];
            float s0[4] = {0.f, 0.f, 0.f, 0.f};
            float s1[4] = {0.f, 0.f, 0.f, 0.f};
            #pragma unroll
            for (int h4 = 0; h4 < 16; h4++) {
                float4 ka = k0r[h4];
                float4 kb = k1r[h4];
                s0[0] = fmaf(q[h4 * 4 + 0], ka.x, s0[0]);
                s0[1] = fmaf(q[h4 * 4 + 1], ka.y, s0[1]);
                s0[2] = fmaf(q[h4 * 4 + 2], ka.z, s0[2]);
                s0[3] = fmaf(q[h4 * 4 + 3], ka.w, s0[3]);
                s1[0] = fmaf(q[h4 * 4 + 0], kb.x, s1[0]);
                s1[1] = fmaf(q[h4 * 4 + 1], kb.y, s1[1]);
                s1[2] = fmaf(q[h4 * 4 + 2], kb.z, s1[2]);
                s1[3] = fmaf(q[h4 * 4 + 3], kb.w, s1[3]);
            }
            float sa = (s0[0] + s0[1]) + (s0[2] + s0[3]);
            float sb = (s1[0] + s1[1]) + (s1[2] + s1[3]);
            Ps[r][j]     = sa;
            Ps[r][j + 1] = sb;
            tmax = fmaxf(tmax, fmaxf(sa, sb));
        }
        if (j < jlim) {
            const float4* k0r = (const float4*)&Ks[j][0];
            float s0[4] = {0.f, 0.f, 0.f, 0.f};
            #pragma unroll
            for (int h4 = 0; h4 < 16; h4++) {
                float4 ka = k0r[h4];
                s0[0] = fmaf(q[h4 * 4 + 0], ka.x, s0[0]);
                s0[1] = fmaf(q[h4 * 4 + 1], ka.y, s0[1]);
                s0[2] = fmaf(q[h4 * 4 + 2], ka.z, s0[2]);
                s0[3] = fmaf(q[h4 * 4 + 3], ka.w, s0[3]);
            }
            float sa = (s0[0] + s0[1]) + (s0[2] + s0[3]);
            Ps[r][j] = sa;
            tmax = fmaxf(tmax, sa);
        }

        const float mnew = fmaxf(m, tmax);
        const float corr = __expf(m - mnew);
        l *= corr;
        #pragma unroll
        for (int h = 0; h < HDIM; h++) acc[h] *= corr;

        // pass 2: exp + PV (j unrolled x2)
        int j2 = 0;
        for (; j2 + 1 < jlim; j2 += 2) {
            float p0 = __expf(Ps[r][j2]     - mnew);
            float p1 = __expf(Ps[r][j2 + 1] - mnew);
            l += p0 + p1;
            const float4* v0r = (const float4*)&Vs[j2][0];
            const float4* v1r = (const float4*)&Vs[j2 + 1][0];
            #pragma unroll
            for (int h4 = 0; h4 < 16; h4++) {
                float4 va = v0r[h4];
                float4 vb = v1r[h4];
                acc[h4 * 4 + 0] = fmaf(p1, vb.x, fmaf(p0, va.x, acc[h4 * 4 + 0]));
                acc[h4 * 4 + 1] = fmaf(p1, vb.y, fmaf(p0, va.y, acc[h4 * 4 + 1]));
                acc[h4 * 4 + 2] = fmaf(p1, vb.z, fmaf(p0, va.z, acc[h4 * 4 + 2]));
                acc[h4 * 4 + 3] = fmaf(p1, vb.w, fmaf(p0, va.w, acc[h4 * 4 + 3]));
            }
        }
        if (j2 < jlim) {
            float p0 = __expf(Ps[r][j2] - mnew);
            l += p0;
            const float4* v0r = (const float4*)&Vs[j2][0];
            #pragma unroll
            for (int h4 = 0; h4 < 16; h4++) {
                float4 va = v0r[h4];
                acc[h4 * 4 + 0] = fmaf(p0, va.x, acc[h4 * 4 + 0]);
                acc[h4 * 4 + 1] = fmaf(p0, va.y, acc[h4 * 4 + 1]);
                acc[h4 * 4 + 2] = fmaf(p0, va.z, acc[h4 * 4 + 2]);
                acc[h4 * 4 + 3] = fmaf(p0, va.w, acc[h4 * 4 + 3]);
            }
        }
        m = mnew;
    }

    const float inv = 1.f / l;
    float4* od = (float4*)&out[grow * HDIM];
    #pragma unroll
    for (int i = 0; i < 16; i++) {
        float4 o;
        o.x = acc[i * 4 + 0] * inv;
        o.y = acc[i * 4 + 1] * inv;
        o.z = acc[i * 4 + 2] * inv;
        o.w = acc[i * 4 + 3] * inv;
        od[i] = o;
    }
}

// ---------------------------------------------------------------------------
extern "C" void kernel_launch(void* const* d_in, const int* in_sizes, int n_in,
                              void* d_out, int out_size)
{
    const float* x  = (const float*)d_in[0];
    const float* wq = (const float*)d_in[1];
    const float* wk = (const float*)d_in[2];
    const float* wv = (const float*)d_in[3];
    float* out = (float*)d_out;

    qkv_proj_mma<<<MROWS / BM, 128>>>(x, wq, wk, wv);
    attn_kernel<<<dim3(TDIM / QTILE, BDIM), 128>>>(out);
}

// round 6
// speedup vs baseline: 3.6767x; 2.6435x over previous
#include <cuda_runtime.h>
#include <math.h>
#include <cstdint>

#define BDIM 16
#define TDIM 2048
#define CDIM 1024
#define HDIM 64
#define MROWS (BDIM * TDIM)   // 32768

// Scratch for projected Q, K, V (device globals: no allocations).
__device__ __align__(16) float g_Q[MROWS * HDIM];
__device__ __align__(16) float g_K[MROWS * HDIM];
__device__ __align__(16) float g_V[MROWS * HDIM];

static __device__ __forceinline__ uint32_t f2tf32(float f) {
    uint32_t u;
    asm("cvt.rna.tf32.f32 %0, %1;" : "=r"(u) : "f"(f));
    return u;
}

#define MMA_TF32(d, a, b0_, b1_) \
    asm volatile( \
        "mma.sync.aligned.m16n8k8.row.col.f32.tf32.tf32.f32 " \
        "{%0,%1,%2,%3}, {%4,%5,%6,%7}, {%8,%9}, {%0,%1,%2,%3};" \
        : "+f"((d)[0]), "+f"((d)[1]), "+f"((d)[2]), "+f"((d)[3]) \
        : "r"((a)[0]), "r"((a)[1]), "r"((a)[2]), "r"((a)[3]), \
          "r"(b0_), "r"(b1_))

// ---------------------------------------------------------------------------
// Kernel 1: QKV projection via mma.sync tf32 (validated in R3).
// ---------------------------------------------------------------------------
#define BM 64
#define BN 192
#define BK 16
#define ASTR 20
#define BSTR 200
#define NCH (CDIM / BK)

__global__ __launch_bounds__(128) void qkv_proj_mma(
    const float* __restrict__ x,
    const float* __restrict__ wq,
    const float* __restrict__ wk,
    const float* __restrict__ wv)
{
    __shared__ uint32_t As[2][BM * ASTR];
    __shared__ uint32_t Bs[2][BK * BSTR];

    const int tid  = threadIdx.x;
    const int wid  = tid >> 5;
    const int lane = tid & 31;
    const int gid  = lane >> 2;
    const int tg   = lane & 3;
    const int wm   = (wid & 1) * 32;
    const int wn   = (wid >> 1) * 96;
    const int m0   = blockIdx.x * BM;

    float acc[2][12][4];
    #pragma unroll
    for (int mi = 0; mi < 2; mi++)
        #pragma unroll
        for (int ni = 0; ni < 12; ni++)
            #pragma unroll
            for (int k = 0; k < 4; k++) acc[mi][ni][k] = 0.f;

    float4 ra[2];
    float4 rb[6];

    auto gload = [&](int c) {
        #pragma unroll
        for (int i = 0; i < 2; i++) {
            int idx = tid + i * 128;
            int row = idx >> 2, c4 = idx & 3;
            ra[i] = *(const float4*)&x[(size_t)(m0 + row) * CDIM + c * BK + c4 * 4];
        }
        #pragma unroll
        for (int i = 0; i < 6; i++) {
            int idx = tid + i * 128;
            int k = idx / 48, n4 = idx % 48;
            const float* wp = (n4 < 16) ? wq : ((n4 < 32) ? wk : wv);
            rb[i] = *(const float4*)&wp[(size_t)(c * BK + k) * HDIM + (n4 & 15) * 4];
        }
    };
    auto sstore = [&](int s) {
        #pragma unroll
        for (int i = 0; i < 2; i++) {
            int idx = tid + i * 128;
            int row = idx >> 2, c4 = idx & 3;
            uint4 t = {f2tf32(ra[i].x), f2tf32(ra[i].y), f2tf32(ra[i].z), f2tf32(ra[i].w)};
            *(uint4*)&As[s][row * ASTR + c4 * 4] = t;
        }
        #pragma unroll
        for (int i = 0; i < 6; i++) {
            int idx = tid + i * 128;
            int k = idx / 48, n4 = idx % 48;
            uint4 t = {f2tf32(rb[i].x), f2tf32(rb[i].y), f2tf32(rb[i].z), f2tf32(rb[i].w)};
            *(uint4*)&Bs[s][k * BSTR + n4 * 4] = t;
        }
    };

    gload(0);
    sstore(0);
    __syncthreads();

    for (int c = 0; c < NCH; c++) {
        const int s = c & 1;
        if (c + 1 < NCH) gload(c + 1);

        #pragma unroll
        for (int ks = 0; ks < 2; ks++) {
            const int k0 = ks * 8;
            uint32_t a[2][4];
            #pragma unroll
            for (int mi = 0; mi < 2; mi++) {
                int r = wm + mi * 16 + gid;
                a[mi][0] = As[s][r * ASTR + k0 + tg];
                a[mi][1] = As[s][(r + 8) * ASTR + k0 + tg];
                a[mi][2] = As[s][r * ASTR + k0 + tg + 4];
                a[mi][3] = As[s][(r + 8) * ASTR + k0 + tg + 4];
            }
            #pragma unroll
            for (int ni = 0; ni < 12; ni++) {
                int n = wn + ni * 8 + gid;
                uint32_t b0 = Bs[s][(k0 + tg) * BSTR + n];
                uint32_t b1 = Bs[s][(k0 + tg + 4) * BSTR + n];
                #pragma unroll
                for (int mi = 0; mi < 2; mi++)
                    MMA_TF32(acc[mi][ni], a[mi], b0, b1);
            }
        }

        if (c + 1 < NCH) sstore(s ^ 1);
        __syncthreads();
    }

    #pragma unroll
    for (int mi = 0; mi < 2; mi++) {
        #pragma unroll
        for (int ni = 0; ni < 12; ni++) {
            int n   = wn + ni * 8 + tg * 2;
            int sec = n >> 6;
            int h   = n & 63;
            float* dst = (sec == 0) ? g_Q : ((sec == 1) ? g_K : g_V);
            int r0 = m0 + wm + mi * 16 + gid;
            *(float2*)&dst[(size_t)r0 * HDIM + h] =
                make_float2(acc[mi][ni][0], acc[mi][ni][1]);
            *(float2*)&dst[(size_t)(r0 + 8) * HDIM + h] =
                make_float2(acc[mi][ni][2], acc[mi][ni][3]);
        }
    }
}

// ---------------------------------------------------------------------------
// Kernel 2: flash attention via mma.sync tf32.
// CTA = 64 q rows, 4 warps (16 rows each), KV tiles of 64.
// ---------------------------------------------------------------------------
#define KSTR 72
#define PSTR 68
#define ATT_SMEM ((2 * 64 * KSTR + 64 * PSTR) * 4)   // 54272 B

__global__ __launch_bounds__(128) void attn_mma(float* __restrict__ out)
{
    extern __shared__ uint32_t sm[];
    uint32_t* Kt = sm;                    // [h][j]  64 x 72
    uint32_t* Vs = sm + 64 * KSTR;        // [j][h]  64 x 72
    uint32_t* Ps = sm + 2 * 64 * KSTR;    // [q][j]  64 x 68

    const int b    = blockIdx.y;
    const int qt   = gridDim.x - 1 - blockIdx.x;   // heavy q-tiles first
    const int tid  = threadIdx.x;
    const int wid  = tid >> 5;
    const int lane = tid & 31;
    const int gid  = lane >> 2;
    const int tg   = lane & 3;
    const int wm   = wid * 16;
    const int q0   = qt * 64;
    const int row0 = q0 + wm + gid;

    // Q A-fragments: resident in registers for the whole kernel (pre-scaled).
    uint32_t qa[8][4];
    {
        const float* Qb = g_Q + ((size_t)b * TDIM + q0 + wm) * HDIM;
        #pragma unroll
        for (int k = 0; k < 8; k++) {
            qa[k][0] = f2tf32(Qb[gid * HDIM + k * 8 + tg] * 0.125f);
            qa[k][1] = f2tf32(Qb[(gid + 8) * HDIM + k * 8 + tg] * 0.125f);
            qa[k][2] = f2tf32(Qb[gid * HDIM + k * 8 + tg + 4] * 0.125f);
            qa[k][3] = f2tf32(Qb[(gid + 8) * HDIM + k * 8 + tg + 4] * 0.125f);
        }
    }

    float o[8][4];
    #pragma unroll
    for (int n = 0; n < 8; n++)
        #pragma unroll
        for (int k = 0; k < 4; k++) o[n][k] = 0.f;
    float m0r = -INFINITY, m1r = -INFINITY;
    float l0 = 0.f, l1 = 0.f;

    const int ntiles = qt + 1;

    for (int kt = 0; kt < ntiles; kt++) {
        const int kv0 = kt * 64;

        __syncthreads();   // all warps done with previous Kt/Vs
        {
            // K: load row j, store transposed [h][j].
            const int j  = tid & 63;
            const int hh = (tid >> 6) * 32;
            const float4* kr = (const float4*)(g_K + ((size_t)b * TDIM + kv0 + j) * HDIM + hh);
            #pragma unroll
            for (int i = 0; i < 8; i++) {
                float4 v = kr[i];
                int h = hh + i * 4;
                Kt[(h + 0) * KSTR + j] = f2tf32(v.x);
                Kt[(h + 1) * KSTR + j] = f2tf32(v.y);
                Kt[(h + 2) * KSTR + j] = f2tf32(v.z);
                Kt[(h + 3) * KSTR + j] = f2tf32(v.w);
            }
            // V: natural [j][h] — FULL tile: 64 rows x 16 float4 = 1024 slots.
            const float* vb = g_V + ((size_t)b * TDIM + kv0) * HDIM;
            #pragma unroll
            for (int i = 0; i < 8; i++) {
                int idx = tid + i * 128;
                int r = idx >> 4, c4 = (idx & 15) * 4;
                float4 v = *(const float4*)&vb[r * HDIM + c4];
                uint4 t = {f2tf32(v.x), f2tf32(v.y), f2tf32(v.z), f2tf32(v.w)};
                *(uint4*)&Vs[r * KSTR + c4] = t;
            }
        }
        __syncthreads();

        // ---- S = Q @ K^T
        float s[8][4];
        #pragma unroll
        for (int n = 0; n < 8; n++) {
            s[n][0] = s[n][1] = s[n][2] = s[n][3] = 0.f;
            #pragma unroll
            for (int k = 0; k < 8; k++) {
                uint32_t b0 = Kt[(k * 8 + tg) * KSTR + n * 8 + gid];
                uint32_t b1 = Kt[(k * 8 + tg + 4) * KSTR + n * 8 + gid];
                MMA_TF32(s[n], qa[k], b0, b1);
            }
        }

        // ---- causal mask (diagonal tile only)
        if (kt == qt) {
            #pragma unroll
            for (int n = 0; n < 8; n++) {
                int j0 = kv0 + n * 8 + 2 * tg;
                if (j0     > row0)     s[n][0] = -1e30f;
                if (j0 + 1 > row0)     s[n][1] = -1e30f;
                if (j0     > row0 + 8) s[n][2] = -1e30f;
                if (j0 + 1 > row0 + 8) s[n][3] = -1e30f;
            }
        }

        // ---- row maxes (4 lanes per row -> 2 shfl.xor)
        float tm0 = -INFINITY, tm1 = -INFINITY;
        #pragma unroll
        for (int n = 0; n < 8; n++) {
            tm0 = fmaxf(tm0, fmaxf(s[n][0], s[n][1]));
            tm1 = fmaxf(tm1, fmaxf(s[n][2], s[n][3]));
        }
        tm0 = fmaxf(tm0, __shfl_xor_sync(0xFFFFFFFFu, tm0, 1));
        tm0 = fmaxf(tm0, __shfl_xor_sync(0xFFFFFFFFu, tm0, 2));
        tm1 = fmaxf(tm1, __shfl_xor_sync(0xFFFFFFFFu, tm1, 1));
        tm1 = fmaxf(tm1, __shfl_xor_sync(0xFFFFFFFFu, tm1, 2));

        const float mn0 = fmaxf(m0r, tm0);
        const float mn1 = fmaxf(m1r, tm1);
        const float c0  = __expf(m0r - mn0);
        const float c1  = __expf(m1r - mn1);
        l0 *= c0;  l1 *= c1;
        #pragma unroll
        for (int n = 0; n < 8; n++) {
            o[n][0] *= c0; o[n][1] *= c0;
            o[n][2] *= c1; o[n][3] *= c1;
        }

        // ---- p = exp(s - m), partial l, write P (tf32) to smem
        #pragma unroll
        for (int n = 0; n < 8; n++) {
            float p0 = __expf(s[n][0] - mn0);
            float p1 = __expf(s[n][1] - mn0);
            float p2 = __expf(s[n][2] - mn1);
            float p3 = __expf(s[n][3] - mn1);
            l0 += p0 + p1;
            l1 += p2 + p3;
            uint2 t01 = {f2tf32(p0), f2tf32(p1)};
            uint2 t23 = {f2tf32(p2), f2tf32(p3)};
            *(uint2*)&Ps[(wm + gid) * PSTR + n * 8 + 2 * tg]     = t01;
            *(uint2*)&Ps[(wm + gid + 8) * PSTR + n * 8 + 2 * tg] = t23;
        }
        m0r = mn0;  m1r = mn1;
        __syncthreads();   // Ps complete before PV mma

        // ---- O += P @ V
        uint32_t pa[8][4];
        #pragma unroll
        for (int k = 0; k < 8; k++) {
            pa[k][0] = Ps[(wm + gid) * PSTR + k * 8 + tg];
            pa[k][1] = Ps[(wm + gid + 8) * PSTR + k * 8 + tg];
            pa[k][2] = Ps[(wm + gid) * PSTR + k * 8 + tg + 4];
            pa[k][3] = Ps[(wm + gid + 8) * PSTR + k * 8 + tg + 4];
        }
        #pragma unroll
        for (int n = 0; n < 8; n++) {
            #pragma unroll
            for (int k = 0; k < 8; k++) {
                uint32_t b0 = Vs[(k * 8 + tg) * KSTR + n * 8 + gid];
                uint32_t b1 = Vs[(k * 8 + tg + 4) * KSTR + n * 8 + gid];
                MMA_TF32(o[n], pa[k], b0, b1);
            }
        }
    }

    // ---- finalize
    l0 += __shfl_xor_sync(0xFFFFFFFFu, l0, 1);
    l0 += __shfl_xor_sync(0xFFFFFFFFu, l0, 2);
    l1 += __shfl_xor_sync(0xFFFFFFFFu, l1, 1);
    l1 += __shfl_xor_sync(0xFFFFFFFFu, l1, 2);
    const float i0 = 1.f / l0;
    const float i1 = 1.f / l1;

    float* ob = out + ((size_t)b * TDIM + q0 + wm) * HDIM;
    #pragma unroll
    for (int n = 0; n < 8; n++) {
        *(float2*)&ob[gid * HDIM + n * 8 + 2 * tg] =
            make_float2(o[n][0] * i0, o[n][1] * i0);
        *(float2*)&ob[(gid + 8) * HDIM + n * 8 + 2 * tg] =
            make_float2(o[n][2] * i1, o[n][3] * i1);
    }
}

// ---------------------------------------------------------------------------
extern "C" void kernel_launch(void* const* d_in, const int* in_sizes, int n_in,
                              void* d_out, int out_size)
{
    const float* x  = (const float*)d_in[0];
    const float* wq = (const float*)d_in[1];
    const float* wk = (const float*)d_in[2];
    const float* wv = (const float*)d_in[3];
    float* out = (float*)d_out;

    qkv_proj_mma<<<MROWS / BM, 128>>>(x, wq, wk, wv);

    cudaFuncSetAttribute(attn_mma, cudaFuncAttributeMaxDynamicSharedMemorySize, ATT_SMEM);
    attn_mma<<<dim3(TDIM / 64, BDIM), 128, ATT_SMEM>>>(out);
}

// round 7
// speedup vs baseline: 3.6792x; 1.0007x over previous
#include <cuda_runtime.h>
#include <math.h>
#include <cstdint>

#define BDIM 16
#define TDIM 2048
#define CDIM 1024
#define HDIM 64
#define MROWS (BDIM * TDIM)   // 32768

// Scratch for projected Q, K, V (device globals: no allocations).
__device__ __align__(16) float g_Q[MROWS * HDIM];
__device__ __align__(16) float g_K[MROWS * HDIM];
__device__ __align__(16) float g_V[MROWS * HDIM];

static __device__ __forceinline__ uint32_t f2tf32(float f) {
    uint32_t u;
    asm("cvt.rna.tf32.f32 %0, %1;" : "=r"(u) : "f"(f));
    return u;
}

#define MMA_TF32(d, a, b0_, b1_) \
    asm volatile( \
        "mma.sync.aligned.m16n8k8.row.col.f32.tf32.tf32.f32 " \
        "{%0,%1,%2,%3}, {%4,%5,%6,%7}, {%8,%9}, {%0,%1,%2,%3};" \
        : "+f"((d)[0]), "+f"((d)[1]), "+f"((d)[2]), "+f"((d)[3]) \
        : "r"((a)[0]), "r"((a)[1]), "r"((a)[2]), "r"((a)[3]), \
          "r"(b0_), "r"(b1_))

// ---------------------------------------------------------------------------
// Kernel 1: QKV projection via mma.sync tf32 (validated in R3).
// ---------------------------------------------------------------------------
#define BM 64
#define BN 192
#define BK 16
#define ASTR 20
#define BSTR 200
#define NCH (CDIM / BK)

__global__ __launch_bounds__(128) void qkv_proj_mma(
    const float* __restrict__ x,
    const float* __restrict__ wq,
    const float* __restrict__ wk,
    const float* __restrict__ wv)
{
    __shared__ uint32_t As[2][BM * ASTR];
    __shared__ uint32_t Bs[2][BK * BSTR];

    const int tid  = threadIdx.x;
    const int wid  = tid >> 5;
    const int lane = tid & 31;
    const int gid  = lane >> 2;
    const int tg   = lane & 3;
    const int wm   = (wid & 1) * 32;
    const int wn   = (wid >> 1) * 96;
    const int m0   = blockIdx.x * BM;

    float acc[2][12][4];
    #pragma unroll
    for (int mi = 0; mi < 2; mi++)
        #pragma unroll
        for (int ni = 0; ni < 12; ni++)
            #pragma unroll
            for (int k = 0; k < 4; k++) acc[mi][ni][k] = 0.f;

    float4 ra[2];
    float4 rb[6];

    auto gload = [&](int c) {
        #pragma unroll
        for (int i = 0; i < 2; i++) {
            int idx = tid + i * 128;
            int row = idx >> 2, c4 = idx & 3;
            ra[i] = *(const float4*)&x[(size_t)(m0 + row) * CDIM + c * BK + c4 * 4];
        }
        #pragma unroll
        for (int i = 0; i < 6; i++) {
            int idx = tid + i * 128;
            int k = idx / 48, n4 = idx % 48;
            const float* wp = (n4 < 16) ? wq : ((n4 < 32) ? wk : wv);
            rb[i] = *(const float4*)&wp[(size_t)(c * BK + k) * HDIM + (n4 & 15) * 4];
        }
    };
    auto sstore = [&](int s) {
        #pragma unroll
        for (int i = 0; i < 2; i++) {
            int idx = tid + i * 128;
            int row = idx >> 2, c4 = idx & 3;
            uint4 t = {f2tf32(ra[i].x), f2tf32(ra[i].y), f2tf32(ra[i].z), f2tf32(ra[i].w)};
            *(uint4*)&As[s][row * ASTR + c4 * 4] = t;
        }
        #pragma unroll
        for (int i = 0; i < 6; i++) {
            int idx = tid + i * 128;
            int k = idx / 48, n4 = idx % 48;
            uint4 t = {f2tf32(rb[i].x), f2tf32(rb[i].y), f2tf32(rb[i].z), f2tf32(rb[i].w)};
            *(uint4*)&Bs[s][k * BSTR + n4 * 4] = t;
        }
    };

    gload(0);
    sstore(0);
    __syncthreads();

    for (int c = 0; c < NCH; c++) {
        const int s = c & 1;
        if (c + 1 < NCH) gload(c + 1);

        #pragma unroll
        for (int ks = 0; ks < 2; ks++) {
            const int k0 = ks * 8;
            uint32_t a[2][4];
            #pragma unroll
            for (int mi = 0; mi < 2; mi++) {
                int r = wm + mi * 16 + gid;
                a[mi][0] = As[s][r * ASTR + k0 + tg];
                a[mi][1] = As[s][(r + 8) * ASTR + k0 + tg];
                a[mi][2] = As[s][r * ASTR + k0 + tg + 4];
                a[mi][3] = As[s][(r + 8) * ASTR + k0 + tg + 4];
            }
            #pragma unroll
            for (int ni = 0; ni < 12; ni++) {
                int n = wn + ni * 8 + gid;
                uint32_t b0 = Bs[s][(k0 + tg) * BSTR + n];
                uint32_t b1 = Bs[s][(k0 + tg + 4) * BSTR + n];
                #pragma unroll
                for (int mi = 0; mi < 2; mi++)
                    MMA_TF32(acc[mi][ni], a[mi], b0, b1);
            }
        }

        if (c + 1 < NCH) sstore(s ^ 1);
        __syncthreads();
    }

    #pragma unroll
    for (int mi = 0; mi < 2; mi++) {
        #pragma unroll
        for (int ni = 0; ni < 12; ni++) {
            int n   = wn + ni * 8 + tg * 2;
            int sec = n >> 6;
            int h   = n & 63;
            float* dst = (sec == 0) ? g_Q : ((sec == 1) ? g_K : g_V);
            int r0 = m0 + wm + mi * 16 + gid;
            *(float2*)&dst[(size_t)r0 * HDIM + h] =
                make_float2(acc[mi][ni][0], acc[mi][ni][1]);
            *(float2*)&dst[(size_t)(r0 + 8) * HDIM + h] =
                make_float2(acc[mi][ni][2], acc[mi][ni][3]);
        }
    }
}

// ---------------------------------------------------------------------------
// Kernel 2: flash attention via mma.sync tf32.
// CTA = 64 q rows, 4 warps (16 rows each), KV tiles of 64.
// ---------------------------------------------------------------------------
#define KSTR 72
#define PSTR 68
#define ATT_SMEM ((2 * 64 * KSTR + 64 * PSTR) * 4)   // 54272 B

__global__ __launch_bounds__(128) void attn_mma(float* __restrict__ out)
{
    extern __shared__ uint32_t sm[];
    uint32_t* Kt = sm;                    // [h][j]  64 x 72
    uint32_t* Vs = sm + 64 * KSTR;        // [j][h]  64 x 72
    uint32_t* Ps = sm + 2 * 64 * KSTR;    // [q][j]  64 x 68

    const int b    = blockIdx.y;
    const int qt   = gridDim.x - 1 - blockIdx.x;   // heavy q-tiles first
    const int tid  = threadIdx.x;
    const int wid  = tid >> 5;
    const int lane = tid & 31;
    const int gid  = lane >> 2;
    const int tg   = lane & 3;
    const int wm   = wid * 16;
    const int q0   = qt * 64;
    const int row0 = q0 + wm + gid;

    // Q A-fragments: resident in registers for the whole kernel (pre-scaled).
    uint32_t qa[8][4];
    {
        const float* Qb = g_Q + ((size_t)b * TDIM + q0 + wm) * HDIM;
        #pragma unroll
        for (int k = 0; k < 8; k++) {
            qa[k][0] = f2tf32(Qb[gid * HDIM + k * 8 + tg] * 0.125f);
            qa[k][1] = f2tf32(Qb[(gid + 8) * HDIM + k * 8 + tg] * 0.125f);
            qa[k][2] = f2tf32(Qb[gid * HDIM + k * 8 + tg + 4] * 0.125f);
            qa[k][3] = f2tf32(Qb[(gid + 8) * HDIM + k * 8 + tg + 4] * 0.125f);
        }
    }

    float o[8][4];
    #pragma unroll
    for (int n = 0; n < 8; n++)
        #pragma unroll
        for (int k = 0; k < 4; k++) o[n][k] = 0.f;
    float m0r = -INFINITY, m1r = -INFINITY;
    float l0 = 0.f, l1 = 0.f;

    const int ntiles = qt + 1;

    for (int kt = 0; kt < ntiles; kt++) {
        const int kv0 = kt * 64;

        __syncthreads();   // all warps done with previous Kt/Vs
        {
            // K: load row j, store transposed [h][j].
            const int j  = tid & 63;
            const int hh = (tid >> 6) * 32;
            const float4* kr = (const float4*)(g_K + ((size_t)b * TDIM + kv0 + j) * HDIM + hh);
            #pragma unroll
            for (int i = 0; i < 8; i++) {
                float4 v = kr[i];
                int h = hh + i * 4;
                Kt[(h + 0) * KSTR + j] = f2tf32(v.x);
                Kt[(h + 1) * KSTR + j] = f2tf32(v.y);
                Kt[(h + 2) * KSTR + j] = f2tf32(v.z);
                Kt[(h + 3) * KSTR + j] = f2tf32(v.w);
            }
            // V: natural [j][h] — FULL tile: 64 rows x 16 float4 = 1024 slots.
            const float* vb = g_V + ((size_t)b * TDIM + kv0) * HDIM;
            #pragma unroll
            for (int i = 0; i < 8; i++) {
                int idx = tid + i * 128;
                int r = idx >> 4, c4 = (idx & 15) * 4;
                float4 v = *(const float4*)&vb[r * HDIM + c4];
                uint4 t = {f2tf32(v.x), f2tf32(v.y), f2tf32(v.z), f2tf32(v.w)};
                *(uint4*)&Vs[r * KSTR + c4] = t;
            }
        }
        __syncthreads();

        // ---- S = Q @ K^T
        float s[8][4];
        #pragma unroll
        for (int n = 0; n < 8; n++) {
            s[n][0] = s[n][1] = s[n][2] = s[n][3] = 0.f;
            #pragma unroll
            for (int k = 0; k < 8; k++) {
                uint32_t b0 = Kt[(k * 8 + tg) * KSTR + n * 8 + gid];
                uint32_t b1 = Kt[(k * 8 + tg + 4) * KSTR + n * 8 + gid];
                MMA_TF32(s[n], qa[k], b0, b1);
            }
        }

        // ---- causal mask (diagonal tile only)
        if (kt == qt) {
            #pragma unroll
            for (int n = 0; n < 8; n++) {
                int j0 = kv0 + n * 8 + 2 * tg;
                if (j0     > row0)     s[n][0] = -1e30f;
                if (j0 + 1 > row0)     s[n][1] = -1e30f;
                if (j0     > row0 + 8) s[n][2] = -1e30f;
                if (j0 + 1 > row0 + 8) s[n][3] = -1e30f;
            }
        }

        // ---- row maxes (4 lanes per row -> 2 shfl.xor)
        float tm0 = -INFINITY, tm1 = -INFINITY;
        #pragma unroll
        for (int n = 0; n < 8; n++) {
            tm0 = fmaxf(tm0, fmaxf(s[n][0], s[n][1]));
            tm1 = fmaxf(tm1, fmaxf(s[n][2], s[n][3]));
        }
        tm0 = fmaxf(tm0, __shfl_xor_sync(0xFFFFFFFFu, tm0, 1));
        tm0 = fmaxf(tm0, __shfl_xor_sync(0xFFFFFFFFu, tm0, 2));
        tm1 = fmaxf(tm1, __shfl_xor_sync(0xFFFFFFFFu, tm1, 1));
        tm1 = fmaxf(tm1, __shfl_xor_sync(0xFFFFFFFFu, tm1, 2));

        const float mn0 = fmaxf(m0r, tm0);
        const float mn1 = fmaxf(m1r, tm1);
        const float c0  = __expf(m0r - mn0);
        const float c1  = __expf(m1r - mn1);
        l0 *= c0;  l1 *= c1;
        #pragma unroll
        for (int n = 0; n < 8; n++) {
            o[n][0] *= c0; o[n][1] *= c0;
            o[n][2] *= c1; o[n][3] *= c1;
        }

        // ---- p = exp(s - m), partial l, write P (tf32) to smem
        #pragma unroll
        for (int n = 0; n < 8; n++) {
            float p0 = __expf(s[n][0] - mn0);
            float p1 = __expf(s[n][1] - mn0);
            float p2 = __expf(s[n][2] - mn1);
            float p3 = __expf(s[n][3] - mn1);
            l0 += p0 + p1;
            l1 += p2 + p3;
            uint2 t01 = {f2tf32(p0), f2tf32(p1)};
            uint2 t23 = {f2tf32(p2), f2tf32(p3)};
            *(uint2*)&Ps[(wm + gid) * PSTR + n * 8 + 2 * tg]     = t01;
            *(uint2*)&Ps[(wm + gid + 8) * PSTR + n * 8 + 2 * tg] = t23;
        }
        m0r = mn0;  m1r = mn1;
        __syncthreads();   // Ps complete before PV mma

        // ---- O += P @ V
        uint32_t pa[8][4];
        #pragma unroll
        for (int k = 0; k < 8; k++) {
            pa[k][0] = Ps[(wm + gid) * PSTR + k * 8 + tg];
            pa[k][1] = Ps[(wm + gid + 8) * PSTR + k * 8 + tg];
            pa[k][2] = Ps[(wm + gid) * PSTR + k * 8 + tg + 4];
            pa[k][3] = Ps[(wm + gid + 8) * PSTR + k * 8 + tg + 4];
        }
        #pragma unroll
        for (int n = 0; n < 8; n++) {
            #pragma unroll
            for (int k = 0; k < 8; k++) {
                uint32_t b0 = Vs[(k * 8 + tg) * KSTR + n * 8 + gid];
                uint32_t b1 = Vs[(k * 8 + tg + 4) * KSTR + n * 8 + gid];
                MMA_TF32(o[n], pa[k], b0, b1);
            }
        }
    }

    // ---- finalize
    l0 += __shfl_xor_sync(0xFFFFFFFFu, l0, 1);
    l0 += __shfl_xor_sync(0xFFFFFFFFu, l0, 2);
    l1 += __shfl_xor_sync(0xFFFFFFFFu, l1, 1);
    l1 += __shfl_xor_sync(0xFFFFFFFFu, l1, 2);
    const float i0 = 1.f / l0;
    const float i1 = 1.f / l1;

    float* ob = out + ((size_t)b * TDIM + q0 + wm) * HDIM;
    #pragma unroll
    for (int n = 0; n < 8; n++) {
        *(float2*)&ob[gid * HDIM + n * 8 + 2 * tg] =
            make_float2(o[n][0] * i0, o[n][1] * i0);
        *(float2*)&ob[(gid + 8) * HDIM + n * 8 + 2 * tg] =
            make_float2(o[n][2] * i1, o[n][3] * i1);
    }
}

// ---------------------------------------------------------------------------
extern "C" void kernel_launch(void* const* d_in, const int* in_sizes, int n_in,
                              void* d_out, int out_size)
{
    const float* x  = (const float*)d_in[0];
    const float* wq = (const float*)d_in[1];
    const float* wk = (const float*)d_in[2];
    const float* wv = (const float*)d_in[3];
    float* out = (float*)d_out;

    qkv_proj_mma<<<MROWS / BM, 128>>>(x, wq, wk, wv);

    cudaFuncSetAttribute(attn_mma, cudaFuncAttributeMaxDynamicSharedMemorySize, ATT_SMEM);
    attn_mma<<<dim3(TDIM / 64, BDIM), 128, ATT_SMEM>>>(out);
}

// round 8
// speedup vs baseline: 5.3664x; 1.4586x over previous
#include <cuda_runtime.h>
#include <cuda_fp16.h>
#include <math.h>
#include <cstdint>

#define BDIM 16
#define TDIM 2048
#define CDIM 1024
#define HDIM 64
#define MROWS (BDIM * TDIM)   // 32768

// fp16 scratch (device globals: no allocations).
//  g_Qh: [b*T + t][h']  (pre-scaled by 1/8, pair-interleaved h)
//  g_Kh: [b*T + t][h']  (pair-interleaved h)
//  g_Vh: [b][h][t']     (transposed, pair-interleaved t)
__device__ __align__(16) __half g_Qh[MROWS * HDIM];
__device__ __align__(16) __half g_Kh[MROWS * HDIM];
__device__ __align__(16) __half g_Vh[(size_t)BDIM * HDIM * TDIM];

// pair interleave within 16-groups: x = a+8b+16c (a<8,b<2) -> 4*(a>>1)+(a&1)+2b+16c
static __device__ __forceinline__ int ih(int x) {
    return 4 * ((x >> 1) & 3) + (x & 1) + 2 * ((x >> 3) & 1) + (x & ~15);
}

static __device__ __forceinline__ uint32_t f2tf32(float f) {
    uint32_t u;
    asm("cvt.rna.tf32.f32 %0, %1;" : "=r"(u) : "f"(f));
    return u;
}
static __device__ __forceinline__ uint32_t h2u(float lo, float hi) {
    __half2 h = __floats2half2_rn(lo, hi);
    return *(uint32_t*)&h;
}
static __device__ __forceinline__ uint32_t smem_u32(const void* p) {
    uint32_t a;
    asm("{ .reg .u64 t; cvta.to.shared.u64 t, %1; cvt.u32.u64 %0, t; }" : "=r"(a) : "l"(p));
    return a;
}
static __device__ __forceinline__ void cp16(uint32_t saddr, const void* g) {
    asm volatile("cp.async.ca.shared.global [%0], [%1], 16;" :: "r"(saddr), "l"(g));
}

#define MMA_TF32(d, a, b0_, b1_) \
    asm volatile( \
        "mma.sync.aligned.m16n8k8.row.col.f32.tf32.tf32.f32 " \
        "{%0,%1,%2,%3}, {%4,%5,%6,%7}, {%8,%9}, {%0,%1,%2,%3};" \
        : "+f"((d)[0]), "+f"((d)[1]), "+f"((d)[2]), "+f"((d)[3]) \
        : "r"((a)[0]), "r"((a)[1]), "r"((a)[2]), "r"((a)[3]), \
          "r"(b0_), "r"(b1_))

#define MMA_F16(d, a, b0_, b1_) \
    asm volatile( \
        "mma.sync.aligned.m16n8k16.row.col.f32.f16.f16.f32 " \
        "{%0,%1,%2,%3}, {%4,%5,%6,%7}, {%8,%9}, {%0,%1,%2,%3};" \
        : "+f"((d)[0]), "+f"((d)[1]), "+f"((d)[2]), "+f"((d)[3]) \
        : "r"((a)[0]), "r"((a)[1]), "r"((a)[2]), "r"((a)[3]), \
          "r"(b0_), "r"(b1_))

// ---------------------------------------------------------------------------
// Kernel 1: QKV projection, tf32 mma mainloop (R3-validated) + fp16 epilogue.
// ---------------------------------------------------------------------------
#define BM 64
#define BN 192
#define BK 16
#define ASTR 20
#define BSTR 200
#define NCH (CDIM / BK)

__global__ __launch_bounds__(128) void qkv_proj_mma(
    const float* __restrict__ x,
    const float* __restrict__ wq,
    const float* __restrict__ wk,
    const float* __restrict__ wv)
{
    __shared__ uint32_t As[2][BM * ASTR];   // 10.0 KB (aliased by stQ in epilogue)
    __shared__ uint32_t Bs[2][BK * BSTR];   // 25.6 KB (aliased by stK/stV)

    const int tid  = threadIdx.x;
    const int wid  = tid >> 5;
    const int lane = tid & 31;
    const int gid  = lane >> 2;
    const int tg   = lane & 3;
    const int wm   = (wid & 1) * 32;
    const int wn   = (wid >> 1) * 96;
    const int m0   = blockIdx.x * BM;

    float acc[2][12][4];
    #pragma unroll
    for (int mi = 0; mi < 2; mi++)
        #pragma unroll
        for (int ni = 0; ni < 12; ni++)
            #pragma unroll
            for (int k = 0; k < 4; k++) acc[mi][ni][k] = 0.f;

    float4 ra[2];
    float4 rb[6];

    auto gload = [&](int c) {
        #pragma unroll
        for (int i = 0; i < 2; i++) {
            int idx = tid + i * 128;
            int row = idx >> 2, c4 = idx & 3;
            ra[i] = *(const float4*)&x[(size_t)(m0 + row) * CDIM + c * BK + c4 * 4];
        }
        #pragma unroll
        for (int i = 0; i < 6; i++) {
            int idx = tid + i * 128;
            int k = idx / 48, n4 = idx % 48;
            const float* wp = (n4 < 16) ? wq : ((n4 < 32) ? wk : wv);
            rb[i] = *(const float4*)&wp[(size_t)(c * BK + k) * HDIM + (n4 & 15) * 4];
        }
    };
    auto sstore = [&](int s) {
        #pragma unroll
        for (int i = 0; i < 2; i++) {
            int idx = tid + i * 128;
            int row = idx >> 2, c4 = idx & 3;
            uint4 t = {f2tf32(ra[i].x), f2tf32(ra[i].y), f2tf32(ra[i].z), f2tf32(ra[i].w)};
            *(uint4*)&As[s][row * ASTR + c4 * 4] = t;
        }
        #pragma unroll
        for (int i = 0; i < 6; i++) {
            int idx = tid + i * 128;
            int k = idx / 48, n4 = idx % 48;
            uint4 t = {f2tf32(rb[i].x), f2tf32(rb[i].y), f2tf32(rb[i].z), f2tf32(rb[i].w)};
            *(uint4*)&Bs[s][k * BSTR + n4 * 4] = t;
        }
    };

    gload(0);
    sstore(0);
    __syncthreads();

    for (int c = 0; c < NCH; c++) {
        const int s = c & 1;
        if (c + 1 < NCH) gload(c + 1);

        #pragma unroll
        for (int ks = 0; ks < 2; ks++) {
            const int k0 = ks * 8;
            uint32_t a[2][4];
            #pragma unroll
            for (int mi = 0; mi < 2; mi++) {
                int r = wm + mi * 16 + gid;
                a[mi][0] = As[s][r * ASTR + k0 + tg];
                a[mi][1] = As[s][(r + 8) * ASTR + k0 + tg];
                a[mi][2] = As[s][r * ASTR + k0 + tg + 4];
                a[mi][3] = As[s][(r + 8) * ASTR + k0 + tg + 4];
            }
            #pragma unroll
            for (int ni = 0; ni < 12; ni++) {
                int n = wn + ni * 8 + gid;
                uint32_t b0 = Bs[s][(k0 + tg) * BSTR + n];
                uint32_t b1 = Bs[s][(k0 + tg + 4) * BSTR + n];
                #pragma unroll
                for (int mi = 0; mi < 2; mi++)
                    MMA_TF32(acc[mi][ni], a[mi], b0, b1);
            }
        }

        if (c + 1 < NCH) sstore(s ^ 1);
        __syncthreads();
    }

    // ---- epilogue: stage fp16 tiles in smem (aliasing As/Bs), coalesced copy out
    __half* stQ = reinterpret_cast<__half*>(&As[0][0]);          // 64x64 halfs (8KB)
    __half* stK = reinterpret_cast<__half*>(&Bs[0][0]);          // 64x64 halfs
    __half* stV = reinterpret_cast<__half*>(&Bs[0][0]) + 4096;   // 64x64 halfs

    #pragma unroll
    for (int mi = 0; mi < 2; mi++) {
        #pragma unroll
        for (int ni = 0; ni < 12; ni++) {
            const int n   = wn + ni * 8 + tg * 2;
            const int sec = n >> 6;
            const int h   = n & 63;
            const int tl  = wm + mi * 16 + gid;
            float a0 = acc[mi][ni][0], a1 = acc[mi][ni][1];
            float a2 = acc[mi][ni][2], a3 = acc[mi][ni][3];
            if (sec == 2) {                      // V: transpose + t-interleave
                const int x0 = ih(tl), x1 = ih(tl + 8);
                stV[h * 64 + x0]       = __float2half(a0);
                stV[(h + 1) * 64 + x0] = __float2half(a1);
                stV[h * 64 + x1]       = __float2half(a2);
                stV[(h + 1) * 64 + x1] = __float2half(a3);
            } else {                             // Q/K: [t][h'] pair-interleaved
                __half* st = (sec == 0) ? stQ : stK;
                const float sc = (sec == 0) ? 0.125f : 1.0f;   // fold 1/sqrt(64) into Q
                const int hp = ih(h);            // even h -> (hp, hp+1) contiguous
                *(__half2*)&st[tl * 64 + hp]       = __floats2half2_rn(a0 * sc, a1 * sc);
                *(__half2*)&st[(tl + 8) * 64 + hp] = __floats2half2_rn(a2 * sc, a3 * sc);
            }
        }
    }
    __syncthreads();

    const int bb = m0 / TDIM;
    const int t0 = m0 % TDIM;
    #pragma unroll
    for (int i = 0; i < 4; i++) {
        int idx = tid + i * 128;                 // 512 uint4 chunks per tile
        int row = idx >> 3, c = idx & 7;
        *(uint4*)(g_Qh + (size_t)(m0 + row) * 64 + c * 8) =
            *(uint4*)(stQ + row * 64 + c * 8);
        *(uint4*)(g_Kh + (size_t)(m0 + row) * 64 + c * 8) =
            *(uint4*)(stK + row * 64 + c * 8);
        *(uint4*)(g_Vh + ((size_t)bb * 64 + row) * TDIM + t0 + c * 8) =
            *(uint4*)(stV + row * 64 + c * 8);
    }
}

// ---------------------------------------------------------------------------
// Kernel 2: flash attention, fp16 m16n8k16, P kept in registers (no smem P).
// CTA = 64 q rows, 4 warps x 16 rows; KV tiles 64; cp.async tile loads.
// Smem rows stride 80 halfs: LDS.64 B-fragments conflict-free.
// ---------------------------------------------------------------------------
#define KVS 80

__global__ __launch_bounds__(128, 4) void attn_f16(float* __restrict__ out)
{
    __shared__ __half Ks[64 * KVS];   // [j][h']  10 KB
    __shared__ __half Vs[64 * KVS];   // [h][j']  10 KB

    const int b    = blockIdx.y;
    const int qt   = gridDim.x - 1 - blockIdx.x;   // heavy q-tiles first
    const int tid  = threadIdx.x;
    const int wid  = tid >> 5;
    const int lane = tid & 31;
    const int gid  = lane >> 2;
    const int tg   = lane & 3;
    const int wm   = wid * 16;
    const int q0   = qt * 64;
    const int row0 = q0 + wm + gid;

    // Q A-fragments (m16k16), resident all kernel. g_Qh pre-scaled + interleaved.
    uint32_t qa[4][4];
    {
        const __half* Qh = g_Qh + ((size_t)b * TDIM + q0 + wm) * 64;
        #pragma unroll
        for (int kb = 0; kb < 4; kb++) {
            uint2 lo = *(const uint2*)(Qh + gid * 64 + 16 * kb + 4 * tg);
            uint2 hi = *(const uint2*)(Qh + (gid + 8) * 64 + 16 * kb + 4 * tg);
            qa[kb][0] = lo.x; qa[kb][1] = hi.x; qa[kb][2] = lo.y; qa[kb][3] = hi.y;
        }
    }

    float o[8][4];
    #pragma unroll
    for (int n = 0; n < 8; n++)
        #pragma unroll
        for (int k = 0; k < 4; k++) o[n][k] = 0.f;
    float m0r = -INFINITY, m1r = -INFINITY;
    float l0 = 0.f, l1 = 0.f;

    const uint32_t ksb = smem_u32(Ks);
    const uint32_t vsb = smem_u32(Vs);
    const int ntiles = qt + 1;

    for (int kt = 0; kt < ntiles; kt++) {
        const int kv0 = kt * 64;

        __syncthreads();   // all warps done with previous tile's smem
        {
            const __half* Kg = g_Kh + ((size_t)b * TDIM + kv0) * 64;
            const __half* Vg = g_Vh + (size_t)b * 64 * TDIM + kv0;
            #pragma unroll
            for (int i = 0; i < 4; i++) {
                int idx = tid + i * 128;         // 512 chunks of 16B per tile
                int row = idx >> 3, c = idx & 7;
                cp16(ksb + row * (KVS * 2) + c * 16, Kg + (size_t)row * 64 + c * 8);
                cp16(vsb + row * (KVS * 2) + c * 16, Vg + (size_t)row * TDIM + c * 8);
            }
        }
        asm volatile("cp.async.commit_group;");
        asm volatile("cp.async.wait_group 0;" ::: "memory");
        __syncthreads();

        // ---- S = Q @ K^T   (B-frag: one LDS.64 per mma, conflict-free)
        float s[8][4];
        #pragma unroll
        for (int n = 0; n < 8; n++) {
            s[n][0] = s[n][1] = s[n][2] = s[n][3] = 0.f;
            #pragma unroll
            for (int k = 0; k < 4; k++) {
                uint2 bb = *(const uint2*)(Ks + (n * 8 + gid) * KVS + 16 * k + 4 * tg);
                MMA_F16(s[n], qa[k], bb.x, bb.y);
            }
        }

        // ---- causal mask (diagonal tile only)
        if (kt == qt) {
            #pragma unroll
            for (int n = 0; n < 8; n++) {
                int j0 = kv0 + n * 8 + 2 * tg;
                if (j0     > row0)     s[n][0] = -1e30f;
                if (j0 + 1 > row0)     s[n][1] = -1e30f;
                if (j0     > row0 + 8) s[n][2] = -1e30f;
                if (j0 + 1 > row0 + 8) s[n][3] = -1e30f;
            }
        }

        // ---- online softmax
        float tm0 = -INFINITY, tm1 = -INFINITY;
        #pragma unroll
        for (int n = 0; n < 8; n++) {
            tm0 = fmaxf(tm0, fmaxf(s[n][0], s[n][1]));
            tm1 = fmaxf(tm1, fmaxf(s[n][2], s[n][3]));
        }
        tm0 = fmaxf(tm0, __shfl_xor_sync(0xFFFFFFFFu, tm0, 1));
        tm0 = fmaxf(tm0, __shfl_xor_sync(0xFFFFFFFFu, tm0, 2));
        tm1 = fmaxf(tm1, __shfl_xor_sync(0xFFFFFFFFu, tm1, 1));
        tm1 = fmaxf(tm1, __shfl_xor_sync(0xFFFFFFFFu, tm1, 2));

        const float mn0 = fmaxf(m0r, tm0);
        const float mn1 = fmaxf(m1r, tm1);
        const float c0  = __expf(m0r - mn0);
        const float c1  = __expf(m1r - mn1);
        l0 *= c0;  l1 *= c1;
        #pragma unroll
        for (int n = 0; n < 8; n++) {
            o[n][0] *= c0; o[n][1] *= c0;
            o[n][2] *= c1; o[n][3] *= c1;
        }
        m0r = mn0;  m1r = mn1;

        // ---- P = exp(S - m) packed to fp16 A-fragments IN REGISTERS
        uint32_t pa[4][4];
        #pragma unroll
        for (int n = 0; n < 8; n++) {
            float p0 = __expf(s[n][0] - mn0);
            float p1 = __expf(s[n][1] - mn0);
            float p2 = __expf(s[n][2] - mn1);
            float p3 = __expf(s[n][3] - mn1);
            l0 += p0 + p1;
            l1 += p2 + p3;
            const int kl = n >> 1;
            if ((n & 1) == 0) { pa[kl][0] = h2u(p0, p1); pa[kl][1] = h2u(p2, p3); }
            else              { pa[kl][2] = h2u(p0, p1); pa[kl][3] = h2u(p2, p3); }
        }

        // ---- O += P @ V   (V transposed+interleaved: one LDS.64 per mma)
        #pragma unroll
        for (int n = 0; n < 8; n++) {
            #pragma unroll
            for (int kl = 0; kl < 4; kl++) {
                uint2 bb = *(const uint2*)(Vs + (n * 8 + gid) * KVS + 16 * kl + 4 * tg);
                MMA_F16(o[n], pa[kl], bb.x, bb.y);
            }
        }
    }

    // ---- finalize
    l0 += __shfl_xor_sync(0xFFFFFFFFu, l0, 1);
    l0 += __shfl_xor_sync(0xFFFFFFFFu, l0, 2);
    l1 += __shfl_xor_sync(0xFFFFFFFFu, l1, 1);
    l1 += __shfl_xor_sync(0xFFFFFFFFu, l1, 2);
    const float i0 = 1.f / l0;
    const float i1 = 1.f / l1;

    float* ob = out + ((size_t)b * TDIM + q0 + wm) * HDIM;
    #pragma unroll
    for (int n = 0; n < 8; n++) {
        *(float2*)&ob[gid * HDIM + n * 8 + 2 * tg] =
            make_float2(o[n][0] * i0, o[n][1] * i0);
        *(float2*)&ob[(gid + 8) * HDIM + n * 8 + 2 * tg] =
            make_float2(o[n][2] * i1, o[n][3] * i1);
    }
}

// ---------------------------------------------------------------------------
extern "C" void kernel_launch(void* const* d_in, const int* in_sizes, int n_in,
                              void* d_out, int out_size)
{
    const float* x  = (const float*)d_in[0];
    const float* wq = (const float*)d_in[1];
    const float* wk = (const float*)d_in[2];
    const float* wv = (const float*)d_in[3];
    float* out = (float*)d_out;

    qkv_proj_mma<<<MROWS / BM, 128>>>(x, wq, wk, wv);
    attn_f16<<<dim3(TDIM / 64, BDIM), 128>>>(out);
}

// round 9
// speedup vs baseline: 7.5347x; 1.4041x over previous
#include <cuda_runtime.h>
#include <cuda_fp16.h>
#include <math.h>
#include <cstdint>

#define BDIM 16
#define TDIM 2048
#define CDIM 1024
#define HDIM 64
#define MROWS (BDIM * TDIM)   // 32768

// fp16 scratch (device globals: no allocations).
__device__ __align__(16) __half g_Qh[MROWS * HDIM];             // [t][h'] interleaved, pre-scaled
__device__ __align__(16) __half g_Kh[MROWS * HDIM];             // [t][h'] interleaved
__device__ __align__(16) __half g_Vh[(size_t)BDIM * HDIM * TDIM];  // [b][h][t'] interleaved
__device__ __align__(16) __half g_Wh[192 * CDIM];               // [n][k'] interleaved

// pair interleave within 16-groups: x=(a+8b+16c), a<8,b<2 -> 4*((a>>1)&3)+(a&1)+2b+16c
static __device__ __forceinline__ int ih(int x) {
    return 4 * ((x >> 1) & 3) + (x & 1) + 2 * ((x >> 3) & 1) + (x & ~15);
}
static __device__ __forceinline__ uint32_t h2u(float lo, float hi) {
    __half2 h = __floats2half2_rn(lo, hi);
    return *(uint32_t*)&h;
}
static __device__ __forceinline__ uint32_t smem_u32(const void* p) {
    uint32_t a;
    asm("{ .reg .u64 t; cvta.to.shared.u64 t, %1; cvt.u32.u64 %0, t; }" : "=r"(a) : "l"(p));
    return a;
}
static __device__ __forceinline__ void cp16(uint32_t saddr, const void* g) {
    asm volatile("cp.async.ca.shared.global [%0], [%1], 16;" :: "r"(saddr), "l"(g));
}

#define MMA_F16(d, a, b0_, b1_) \
    asm volatile( \
        "mma.sync.aligned.m16n8k16.row.col.f32.f16.f16.f32 " \
        "{%0,%1,%2,%3}, {%4,%5,%6,%7}, {%8,%9}, {%0,%1,%2,%3};" \
        : "+f"((d)[0]), "+f"((d)[1]), "+f"((d)[2]), "+f"((d)[3]) \
        : "r"((a)[0]), "r"((a)[1]), "r"((a)[2]), "r"((a)[3]), \
          "r"(b0_), "r"(b1_))

// ---------------------------------------------------------------------------
// Kernel 0: convert weights to fp16, [n][k'] pair-interleaved (B layout).
// ---------------------------------------------------------------------------
__global__ __launch_bounds__(256) void cvt_w(
    const float* __restrict__ wq,
    const float* __restrict__ wk,
    const float* __restrict__ wv)
{
    const int n   = blockIdx.x;                 // 0..191
    const float* wp = (n < 64) ? wq : ((n < 128) ? wk : wv);
    const int col = n & 63;
    #pragma unroll
    for (int i = 0; i < 4; i++) {
        int k = threadIdx.x + i * 256;
        g_Wh[n * CDIM + ih(k)] = __float2half(wp[(size_t)k * HDIM + col]);
    }
}

// ---------------------------------------------------------------------------
// Kernel 1: QKV projection, fp16 m16n8k16 mainloop.
// CTA 128x192, K-chunk 32, 256 threads (8 warps, warp tile 32x96).
// A: fp32 LDG -> cvt -> smem [m][k'] (stride 48); B: cp.async from g_Wh.
// ---------------------------------------------------------------------------
#define XSTR 48                      // smem row stride in halfs
#define PA_H (128 * XSTR)            // A stage size in halfs (6144)
#define PB_H (192 * XSTR)            // B stage size in halfs (9216)
#define PROJ_SMEM ((2 * PA_H + 2 * PB_H) * 2)   // 61440 B
#define NCH (CDIM / 32)              // 32 chunks

__global__ __launch_bounds__(256) void qkv_proj_f16(const float* __restrict__ x)
{
    extern __shared__ __half smh[];
    __half* Ax = smh;                // [2][128*48]
    __half* Bw = smh + 2 * PA_H;     // [2][192*48]

    const int tid  = threadIdx.x;
    const int wid  = tid >> 5;
    const int lane = tid & 31;
    const int gid  = lane >> 2;
    const int tg   = lane & 3;
    const int wm   = (wid >> 1) * 32;
    const int wn   = (wid & 1) * 96;
    const int m0   = blockIdx.x * 128;
    const uint32_t bwb = smem_u32(Bw);

    float acc[2][12][4];
    #pragma unroll
    for (int mi = 0; mi < 2; mi++)
        #pragma unroll
        for (int ni = 0; ni < 12; ni++)
            #pragma unroll
            for (int k = 0; k < 4; k++) acc[mi][ni][k] = 0.f;

    float4 ra[4];

    auto gloadA = [&](int c) {
        #pragma unroll
        for (int i = 0; i < 4; i++) {
            int idx = tid + i * 256;             // 1024 float4 slots (128x32)
            int row = idx >> 3, c4 = idx & 7;
            ra[i] = *(const float4*)&x[(size_t)(m0 + row) * CDIM + c * 32 + c4 * 4];
        }
    };
    auto sstoreA = [&](int s) {
        #pragma unroll
        for (int i = 0; i < 4; i++) {
            int idx = tid + i * 256;
            int row = idx >> 3, c4 = idx & 7;
            int k = c4 * 4;
            __half* base = Ax + s * PA_H + row * XSTR;
            *(__half2*)&base[ih(k)]     = __floats2half2_rn(ra[i].x, ra[i].y);
            *(__half2*)&base[ih(k + 2)] = __floats2half2_rn(ra[i].z, ra[i].w);
        }
    };
    auto cpB = [&](int c, int s) {
        #pragma unroll
        for (int i = 0; i < 3; i++) {
            int idx = tid + i * 256;             // 768 16B chunks (192 rows x 4)
            int row = idx >> 2, cc = idx & 3;
            cp16(bwb + s * (PB_H * 2) + row * (XSTR * 2) + cc * 16,
                 g_Wh + (size_t)row * CDIM + c * 32 + cc * 8);
        }
    };

    gloadA(0);
    cpB(0, 0);
    asm volatile("cp.async.commit_group;");
    sstoreA(0);

    for (int c = 0; c < NCH; c++) {
        const int s = c & 1;
        if (c + 1 < NCH) {
            gloadA(c + 1);
            cpB(c + 1, s ^ 1);
            asm volatile("cp.async.commit_group;");
        }
        if (c + 1 < NCH) { asm volatile("cp.async.wait_group 1;" ::: "memory"); }
        else             { asm volatile("cp.async.wait_group 0;" ::: "memory"); }
        __syncthreads();

        const __half* As = Ax + s * PA_H;
        const __half* Bs = Bw + s * PB_H;
        #pragma unroll
        for (int kb = 0; kb < 2; kb++) {
            uint32_t a[2][4];
            #pragma unroll
            for (int mi = 0; mi < 2; mi++) {
                int row = wm + mi * 16 + gid;
                uint2 lo = *(const uint2*)&As[row * XSTR + kb * 16 + tg * 4];
                uint2 hi = *(const uint2*)&As[(row + 8) * XSTR + kb * 16 + tg * 4];
                a[mi][0] = lo.x; a[mi][1] = hi.x; a[mi][2] = lo.y; a[mi][3] = hi.y;
            }
            #pragma unroll
            for (int ni = 0; ni < 12; ni++) {
                uint2 bb = *(const uint2*)&Bs[(wn + ni * 8 + gid) * XSTR + kb * 16 + tg * 4];
                MMA_F16(acc[0][ni], a[0], bb.x, bb.y);
                MMA_F16(acc[1][ni], a[1], bb.x, bb.y);
            }
        }

        if (c + 1 < NCH) sstoreA(s ^ 1);
        __syncthreads();
    }

    // ---- epilogue: stage fp16 tiles (aliasing smem), coalesced copy out
    __half* stQ = smh;            // [t 128][h' 64]
    __half* stK = smh + 8192;
    __half* stV = smh + 16384;    // [h 64][t' 128]

    #pragma unroll
    for (int mi = 0; mi < 2; mi++) {
        #pragma unroll
        for (int ni = 0; ni < 12; ni++) {
            const int n   = wn + ni * 8 + tg * 2;
            const int sec = n >> 6;
            const int h   = n & 63;
            const int tl  = wm + mi * 16 + gid;
            float a0 = acc[mi][ni][0], a1 = acc[mi][ni][1];
            float a2 = acc[mi][ni][2], a3 = acc[mi][ni][3];
            if (sec == 2) {                      // V: transpose + t-interleave
                const int x0 = ih(tl), x1 = ih(tl + 8);
                stV[h * 128 + x0]       = __float2half(a0);
                stV[(h + 1) * 128 + x0] = __float2half(a1);
                stV[h * 128 + x1]       = __float2half(a2);
                stV[(h + 1) * 128 + x1] = __float2half(a3);
            } else {                             // Q/K: [t][h'] pair-interleaved
                __half* st = (sec == 0) ? stQ : stK;
                const float sc = (sec == 0) ? 0.125f : 1.0f;
                const int hp = ih(h);
                *(__half2*)&st[tl * 64 + hp]       = __floats2half2_rn(a0 * sc, a1 * sc);
                *(__half2*)&st[(tl + 8) * 64 + hp] = __floats2half2_rn(a2 * sc, a3 * sc);
            }
        }
    }
    __syncthreads();

    const int bb = m0 / TDIM;
    const int t0 = m0 % TDIM;
    #pragma unroll
    for (int i = 0; i < 4; i++) {
        int idx = tid + i * 256;                 // 1024 uint4 chunks
        int row = idx >> 3, c = idx & 7;
        *(uint4*)(g_Qh + (size_t)(m0 + row) * 64 + c * 8) =
            *(uint4*)(stQ + row * 64 + c * 8);
        *(uint4*)(g_Kh + (size_t)(m0 + row) * 64 + c * 8) =
            *(uint4*)(stK + row * 64 + c * 8);
    }
    #pragma unroll
    for (int i = 0; i < 4; i++) {
        int idx = tid + i * 256;                 // 1024 uint4 chunks (64 x 16)
        int h = idx >> 4, c = idx & 15;
        *(uint4*)(g_Vh + ((size_t)bb * 64 + h) * TDIM + t0 + c * 8) =
            *(uint4*)(stV + h * 128 + c * 8);
    }
}

// ---------------------------------------------------------------------------
// Kernel 2: flash attention, fp16 m16n8k16, P in registers (R7-validated).
// ---------------------------------------------------------------------------
#define KVS 80

__global__ __launch_bounds__(128, 4) void attn_f16(float* __restrict__ out)
{
    __shared__ __half Ks[64 * KVS];   // [j][h']  10 KB
    __shared__ __half Vs[64 * KVS];   // [h][j']  10 KB

    const int b    = blockIdx.y;
    const int qt   = gridDim.x - 1 - blockIdx.x;   // heavy q-tiles first
    const int tid  = threadIdx.x;
    const int wid  = tid >> 5;
    const int lane = tid & 31;
    const int gid  = lane >> 2;
    const int tg   = lane & 3;
    const int wm   = wid * 16;
    const int q0   = qt * 64;
    const int row0 = q0 + wm + gid;

    uint32_t qa[4][4];
    {
        const __half* Qh = g_Qh + ((size_t)b * TDIM + q0 + wm) * 64;
        #pragma unroll
        for (int kb = 0; kb < 4; kb++) {
            uint2 lo = *(const uint2*)(Qh + gid * 64 + 16 * kb + 4 * tg);
            uint2 hi = *(const uint2*)(Qh + (gid + 8) * 64 + 16 * kb + 4 * tg);
            qa[kb][0] = lo.x; qa[kb][1] = hi.x; qa[kb][2] = lo.y; qa[kb][3] = hi.y;
        }
    }

    float o[8][4];
    #pragma unroll
    for (int n = 0; n < 8; n++)
        #pragma unroll
        for (int k = 0; k < 4; k++) o[n][k] = 0.f;
    float m0r = -INFINITY, m1r = -INFINITY;
    float l0 = 0.f, l1 = 0.f;

    const uint32_t ksb = smem_u32(Ks);
    const uint32_t vsb = smem_u32(Vs);
    const int ntiles = qt + 1;

    for (int kt = 0; kt < ntiles; kt++) {
        const int kv0 = kt * 64;

        __syncthreads();
        {
            const __half* Kg = g_Kh + ((size_t)b * TDIM + kv0) * 64;
            const __half* Vg = g_Vh + (size_t)b * 64 * TDIM + kv0;
            #pragma unroll
            for (int i = 0; i < 4; i++) {
                int idx = tid + i * 128;
                int row = idx >> 3, c = idx & 7;
                cp16(ksb + row * (KVS * 2) + c * 16, Kg + (size_t)row * 64 + c * 8);
                cp16(vsb + row * (KVS * 2) + c * 16, Vg + (size_t)row * TDIM + c * 8);
            }
        }
        asm volatile("cp.async.commit_group;");
        asm volatile("cp.async.wait_group 0;" ::: "memory");
        __syncthreads();

        float s[8][4];
        #pragma unroll
        for (int n = 0; n < 8; n++) {
            s[n][0] = s[n][1] = s[n][2] = s[n][3] = 0.f;
            #pragma unroll
            for (int k = 0; k < 4; k++) {
                uint2 bb = *(const uint2*)(Ks + (n * 8 + gid) * KVS + 16 * k + 4 * tg);
                MMA_F16(s[n], qa[k], bb.x, bb.y);
            }
        }

        if (kt == qt) {
            #pragma unroll
            for (int n = 0; n < 8; n++) {
                int j0 = kv0 + n * 8 + 2 * tg;
                if (j0     > row0)     s[n][0] = -1e30f;
                if (j0 + 1 > row0)     s[n][1] = -1e30f;
                if (j0     > row0 + 8) s[n][2] = -1e30f;
                if (j0 + 1 > row0 + 8) s[n][3] = -1e30f;
            }
        }

        float tm0 = -INFINITY, tm1 = -INFINITY;
        #pragma unroll
        for (int n = 0; n < 8; n++) {
            tm0 = fmaxf(tm0, fmaxf(s[n][0], s[n][1]));
            tm1 = fmaxf(tm1, fmaxf(s[n][2], s[n][3]));
        }
        tm0 = fmaxf(tm0, __shfl_xor_sync(0xFFFFFFFFu, tm0, 1));
        tm0 = fmaxf(tm0, __shfl_xor_sync(0xFFFFFFFFu, tm0, 2));
        tm1 = fmaxf(tm1, __shfl_xor_sync(0xFFFFFFFFu, tm1, 1));
        tm1 = fmaxf(tm1, __shfl_xor_sync(0xFFFFFFFFu, tm1, 2));

        const float mn0 = fmaxf(m0r, tm0);
        const float mn1 = fmaxf(m1r, tm1);
        const float c0  = __expf(m0r - mn0);
        const float c1  = __expf(m1r - mn1);
        l0 *= c0;  l1 *= c1;
        #pragma unroll
        for (int n = 0; n < 8; n++) {
            o[n][0] *= c0; o[n][1] *= c0;
            o[n][2] *= c1; o[n][3] *= c1;
        }
        m0r = mn0;  m1r = mn1;

        uint32_t pa[4][4];
        #pragma unroll
        for (int n = 0; n < 8; n++) {
            float p0 = __expf(s[n][0] - mn0);
            float p1 = __expf(s[n][1] - mn0);
            float p2 = __expf(s[n][2] - mn1);
            float p3 = __expf(s[n][3] - mn1);
            l0 += p0 + p1;
            l1 += p2 + p3;
            const int kl = n >> 1;
            if ((n & 1) == 0) { pa[kl][0] = h2u(p0, p1); pa[kl][1] = h2u(p2, p3); }
            else              { pa[kl][2] = h2u(p0, p1); pa[kl][3] = h2u(p2, p3); }
        }

        #pragma unroll
        for (int n = 0; n < 8; n++) {
            #pragma unroll
            for (int kl = 0; kl < 4; kl++) {
                uint2 bb = *(const uint2*)(Vs + (n * 8 + gid) * KVS + 16 * kl + 4 * tg);
                MMA_F16(o[n], pa[kl], bb.x, bb.y);
            }
        }
    }

    l0 += __shfl_xor_sync(0xFFFFFFFFu, l0, 1);
    l0 += __shfl_xor_sync(0xFFFFFFFFu, l0, 2);
    l1 += __shfl_xor_sync(0xFFFFFFFFu, l1, 1);
    l1 += __shfl_xor_sync(0xFFFFFFFFu, l1, 2);
    const float i0 = 1.f / l0;
    const float i1 = 1.f / l1;

    float* ob = out + ((size_t)b * TDIM + q0 + wm) * HDIM;
    #pragma unroll
    for (int n = 0; n < 8; n++) {
        *(float2*)&ob[gid * HDIM + n * 8 + 2 * tg] =
            make_float2(o[n][0] * i0, o[n][1] * i0);
        *(float2*)&ob[(gid + 8) * HDIM + n * 8 + 2 * tg] =
            make_float2(o[n][2] * i1, o[n][3] * i1);
    }
}

// ---------------------------------------------------------------------------
extern "C" void kernel_launch(void* const* d_in, const int* in_sizes, int n_in,
                              void* d_out, int out_size)
{
    const float* x  = (const float*)d_in[0];
    const float* wq = (const float*)d_in[1];
    const float* wk = (const float*)d_in[2];
    const float* wv = (const float*)d_in[3];
    float* out = (float*)d_out;

    cvt_w<<<192, 256>>>(wq, wk, wv);

    cudaFuncSetAttribute(qkv_proj_f16, cudaFuncAttributeMaxDynamicSharedMemorySize, PROJ_SMEM);
    qkv_proj_f16<<<MROWS / 128, 256, PROJ_SMEM>>>(x);

    attn_f16<<<dim3(TDIM / 64, BDIM), 128>>>(out);
}